// round 13
// baseline (speedup 1.0000x reference)
#include <cuda_runtime.h>
#include <cuda_fp16.h>
#include <cuda_bf16.h>
#include <cstdint>

// ============================================================================
// Problem sizes (fixed)
// ============================================================================
#define BATCH 4096
#define HID   4096
#define VOC   4096
#define KIN   8192      // V + H
#define N4    16384     // 4*H (f,i,c,o stacked along N)

// ============================================================================
// Device scratch (static __device__ arrays — no cudaMalloc anywhere)
// ============================================================================
__device__ __half g_xh   [(size_t)BATCH * KIN];   //  64 MB  A of GEMM1
__device__ __half g_W4   [(size_t)N4    * KIN];   // 256 MB  B of GEMM1 (Wf;Wi;Wc;Wo)
__device__ __half g_Wout [(size_t)VOC   * HID];   //  32 MB  B of GEMM2
__device__ __half g_gates[(size_t)BATCH * N4];    // 128 MB  activated gates
__device__ __half g_hnew [(size_t)BATCH * HID];   //  32 MB  A of GEMM2
__device__ float  g_logits[(size_t)BATCH * VOC];  //  64 MB
__device__ float  g_bias4[N4];

// ============================================================================
// Baseline-ISA helpers (sm_80/75 features only — target is plain sm_103)
// ============================================================================
__device__ __forceinline__ uint32_t smem_u32(const void* p) {
    uint32_t a;
    asm("{ .reg .u64 t; cvta.to.shared.u64 t, %1; cvt.u32.u64 %0, t; }"
        : "=r"(a) : "l"(p));
    return a;
}

__device__ __forceinline__ void cp_async16(uint32_t dst, const void* src) {
    asm volatile("cp.async.cg.shared.global [%0], [%1], 16;" :: "r"(dst), "l"(src));
}
#define CP_COMMIT() asm volatile("cp.async.commit_group;" ::: "memory")
#define CP_WAIT(n)  asm volatile("cp.async.wait_group %0;" :: "n"(n) : "memory")

__device__ __forceinline__ void ldmx4(uint32_t* r, uint32_t addr) {
    asm volatile("ldmatrix.sync.aligned.m8n8.x4.shared.b16 {%0,%1,%2,%3}, [%4];"
                 : "=r"(r[0]), "=r"(r[1]), "=r"(r[2]), "=r"(r[3]) : "r"(addr));
}

__device__ __forceinline__ void mma16816(float* d, const uint32_t* a, const uint32_t* b) {
    asm volatile(
        "mma.sync.aligned.m16n8k16.row.col.f32.f16.f16.f32 "
        "{%0,%1,%2,%3}, {%4,%5,%6,%7}, {%8,%9}, {%0,%1,%2,%3};"
        : "+f"(d[0]), "+f"(d[1]), "+f"(d[2]), "+f"(d[3])
        : "r"(a[0]), "r"(a[1]), "r"(a[2]), "r"(a[3]), "r"(b[0]), "r"(b[1]));
}

// ============================================================================
// GEMM: C[M,N] = A[M,K] * B[N,K]^T, fp16 in / fp32 accum.
// BM=BN=128, BK=32, 256 thr (8 warps, 2Mx4N), 4-stage cp.async pipeline.
// SMEM rows padded to 80B (5 cells of 16B): (5r+c) mod 8 is a permutation of
// the 8 bank-groups -> conflict-free cp.async stores AND ldmatrix loads.
// ============================================================================
#define BK        32
#define NST       4
#define ROW_B     80                         // 64B data + 16B pad
#define TILE_B    (128 * ROW_B)              // 10240 B per operand tile
#define STAGE_B   (2 * TILE_B)               // A tile + B tile = 20480 B
#define GEMM_SMEM (NST * STAGE_B)            // 81920 B

__device__ __forceinline__ void load_block(
    const __half* __restrict__ A, const __half* __restrict__ Bm,
    int K, int m0, int n0, uint32_t sb, int kb, int tid)
{
    uint32_t stb = sb + (uint32_t)(kb & (NST - 1)) * STAGE_B;
    const __half* srcA = A  + (size_t)m0 * K + (size_t)kb * BK;
    const __half* srcB = Bm + (size_t)n0 * K + (size_t)kb * BK;
#pragma unroll
    for (int q = 0; q < 4; q++) {
        int id = q * 256 + tid;              // 0..1023 : 512 A chunks, 512 B chunks
        int half_sel = id >> 9;              // 0 = A, 1 = B
        int c = id & 511;
        int r = c >> 2, cell = c & 3;
        uint32_t dst = stb + (uint32_t)half_sel * TILE_B
                     + (uint32_t)r * ROW_B + (uint32_t)cell * 16;
        const __half* src = (half_sel ? srcB : srcA) + (size_t)r * K + cell * 8;
        cp_async16(dst, src);
    }
}

// EPI 0: gates (bias + sigmoid/tanh, fp16 out, ld=16384)
// EPI 1: logits (bias only, fp32 out, ld=4096)
template <int EPI>
__global__ void __launch_bounds__(256, 2) gemm_hmma(
    const __half* __restrict__ A, const __half* __restrict__ Bm,
    int K, int ldn, const float* __restrict__ bias, void* __restrict__ outp)
{
    extern __shared__ char smem[];
    uint32_t sb = smem_u32(smem);
    int tid = threadIdx.x;
    int w = tid >> 5, l = tid & 31;
    int wm = (w & 1) * 64;                   // warp M offset within CTA tile
    int wn = (w >> 1) * 32;                  // warp N offset
    int m0 = blockIdx.x * 128;
    int n0 = blockIdx.y * 128;
    int KB = K / BK;

    // per-thread ldmatrix row indices (constant across k)
    int a_row = wm + (l & 15);               // + mi*16
    int a_koff = ((l >> 4) & 1) * 16;        // bytes: k0-7 vs k8-15 halves
    int b_row = wn + ((l >> 4) << 3) + (l & 7);  // + bi*16
    int b_koff = ((l >> 3) & 1) * 16;

    float acc[4][4][4];
#pragma unroll
    for (int i = 0; i < 4; i++)
#pragma unroll
        for (int j = 0; j < 4; j++)
#pragma unroll
            for (int k = 0; k < 4; k++) acc[i][j][k] = 0.f;

    // prologue: fill NST-1 stages
#pragma unroll
    for (int kb = 0; kb < NST - 1; kb++) {
        load_block(A, Bm, K, m0, n0, sb, kb, tid);
        CP_COMMIT();
    }

    for (int kb = 0; kb < KB; kb++) {
        CP_WAIT(2);                          // stage kb resident
        __syncthreads();
        if (kb + NST - 1 < KB)
            load_block(A, Bm, K, m0, n0, sb, kb + NST - 1, tid);
        CP_COMMIT();

        uint32_t sa = sb + (uint32_t)(kb & (NST - 1)) * STAGE_B;
        uint32_t sB = sa + TILE_B;
#pragma unroll
        for (int ks = 0; ks < 2; ks++) {     // two k16 steps per BK=32
            uint32_t af[4][4], bf[2][4];
#pragma unroll
            for (int mi = 0; mi < 4; mi++)
                ldmx4(af[mi], sa + (uint32_t)(a_row + mi * 16) * ROW_B
                                 + (uint32_t)(ks * 32 + a_koff));
#pragma unroll
            for (int bi = 0; bi < 2; bi++)
                ldmx4(bf[bi], sB + (uint32_t)(b_row + bi * 16) * ROW_B
                                 + (uint32_t)(ks * 32 + b_koff));
#pragma unroll
            for (int mi = 0; mi < 4; mi++) {
#pragma unroll
                for (int ni = 0; ni < 4; ni++)
                    mma16816(acc[mi][ni], af[mi], &bf[ni >> 1][(ni & 1) * 2]);
            }
        }
        __syncthreads();                     // stage reuse guard
    }

    // ---------------- epilogue (from registers, fused activation) -----------
    int r_lo = l >> 2;                       // +0 / +8 within m16
    int cq = (l & 3) * 2;                    // column pair within n8
#pragma unroll
    for (int mi = 0; mi < 4; mi++) {
#pragma unroll
        for (int half_m = 0; half_m < 2; half_m++) {
            int row = m0 + wm + mi * 16 + r_lo + half_m * 8;
#pragma unroll
            for (int ni = 0; ni < 4; ni++) {
                int col = n0 + wn + ni * 8 + cq;
                float v0 = acc[mi][ni][half_m * 2 + 0] + bias[col];
                float v1 = acc[mi][ni][half_m * 2 + 1] + bias[col + 1];
                if (EPI == 0) {
                    int gate = n0 >> 12;     // BN=128 tile never straddles a gate
                    if (gate == 2) { v0 = tanhf(v0); v1 = tanhf(v1); }
                    else {
                        v0 = 1.f / (1.f + __expf(-v0));
                        v1 = 1.f / (1.f + __expf(-v1));
                    }
                    *(__half2*)((__half*)outp + (size_t)row * ldn + col) =
                        __floats2half2_rn(v0, v1);
                } else {
                    float2 o = make_float2(v0, v1);
                    *(float2*)((float*)outp + (size_t)row * ldn + col) = o;
                }
            }
        }
    }
}

// ============================================================================
// Small kernels
// ============================================================================
__global__ void pack_xh_k(const float* __restrict__ x, const float* __restrict__ h,
                          __half* __restrict__ xh)
{
    int t = blockIdx.x * blockDim.x + threadIdx.x;   // half2 index, exact grid
    int b = t >> 12;
    int p = t & 4095;
    int col = p * 2;
    const float* src = (col < VOC) ? (x + (size_t)b * VOC + col)
                                   : (h + (size_t)b * HID + (col - VOC));
    float2 v = *(const float2*)src;
    ((__half2*)xh)[(size_t)b * 4096 + p] = __floats2half2_rn(v.x, v.y);
}

__global__ void f2h_k(const float* __restrict__ s, __half* __restrict__ d)
{
    size_t i = (size_t)blockIdx.x * blockDim.x + threadIdx.x;
    float2 v = ((const float2*)s)[i];
    ((__half2*)d)[i] = __floats2half2_rn(v.x, v.y);
}

__global__ void bias4_k(const float* __restrict__ bf, const float* __restrict__ bi,
                        const float* __restrict__ bc, const float* __restrict__ bo,
                        float* __restrict__ b4)
{
    int i = blockIdx.x * blockDim.x + threadIdx.x;   // 16384 exact
    int g = i >> 12, j = i & 4095;
    const float* p = (g == 0) ? bf : (g == 1) ? bi : (g == 2) ? bc : bo;
    b4[i] = p[j];
}

__global__ void combine_k(const __half* __restrict__ gates, const float* __restrict__ c,
                          __half* __restrict__ hnew)
{
    int t = blockIdx.x * blockDim.x + threadIdx.x;   // B*H/2 half2 units, exact
    int b = t >> 11;
    int jj = t & 2047;
    size_t h2base = (size_t)b * 8192;
    float2 f  = __half22float2(((const __half2*)gates)[h2base + jj]);
    float2 ig = __half22float2(((const __half2*)gates)[h2base + 2048 + jj]);
    float2 gg = __half22float2(((const __half2*)gates)[h2base + 4096 + jj]);
    float2 oo = __half22float2(((const __half2*)gates)[h2base + 6144 + jj]);
    float2 cv = ((const float2*)c)[(size_t)b * 2048 + jj];
    float c0 = cv.x * f.x + gg.x * ig.x;
    float c1 = cv.y * f.y + gg.y * ig.y;
    ((__half2*)hnew)[(size_t)b * 2048 + jj] =
        __floats2half2_rn(tanhf(c0) * oo.x, tanhf(c1) * oo.y);
}

__global__ void __launch_bounds__(256) softmax_k(const float* __restrict__ lg,
                                                 float* __restrict__ out)
{
    int row = blockIdx.x, tid = threadIdx.x;
    const float4* lp = (const float4*)(lg + (size_t)row * VOC);
    float4* op = (float4*)(out + (size_t)row * VOC);
    float4 a[4];
    float mx = -1e30f;
#pragma unroll
    for (int k = 0; k < 4; k++) {
        a[k] = lp[tid + k * 256];
        mx = fmaxf(mx, fmaxf(fmaxf(a[k].x, a[k].y), fmaxf(a[k].z, a[k].w)));
    }
    __shared__ float red[8];
#pragma unroll
    for (int off = 16; off; off >>= 1) mx = fmaxf(mx, __shfl_xor_sync(~0u, mx, off));
    if ((tid & 31) == 0) red[tid >> 5] = mx;
    __syncthreads();
    float bm = red[0];
#pragma unroll
    for (int i = 1; i < 8; i++) bm = fmaxf(bm, red[i]);
    __syncthreads();

    float s = 0.f;
#pragma unroll
    for (int k = 0; k < 4; k++) {
        a[k].x = __expf(a[k].x - bm); a[k].y = __expf(a[k].y - bm);
        a[k].z = __expf(a[k].z - bm); a[k].w = __expf(a[k].w - bm);
        s += a[k].x + a[k].y + a[k].z + a[k].w;
    }
#pragma unroll
    for (int off = 16; off; off >>= 1) s += __shfl_xor_sync(~0u, s, off);
    if ((tid & 31) == 0) red[tid >> 5] = s;
    __syncthreads();
    float tot = 0.f;
#pragma unroll
    for (int i = 0; i < 8; i++) tot += red[i];
    float inv = 1.f / tot;
#pragma unroll
    for (int k = 0; k < 4; k++) {
        a[k].x *= inv; a[k].y *= inv; a[k].z *= inv; a[k].w *= inv;
        op[tid + k * 256] = a[k];
    }
}

// ============================================================================
// Launcher
// ============================================================================
extern "C" void kernel_launch(void* const* d_in, const int* in_sizes, int n_in,
                              void* d_out, int out_size)
{
    const float* x    = (const float*)d_in[0];
    const float* h    = (const float*)d_in[1];
    const float* c    = (const float*)d_in[2];
    const float* Wf   = (const float*)d_in[3];
    const float* bf   = (const float*)d_in[4];
    const float* Wi   = (const float*)d_in[5];
    const float* bi   = (const float*)d_in[6];
    const float* Wc   = (const float*)d_in[7];
    const float* bc   = (const float*)d_in[8];
    const float* Wo   = (const float*)d_in[9];
    const float* bo   = (const float*)d_in[10];
    const float* Wout = (const float*)d_in[11];
    const float* bout = (const float*)d_in[12];
    float* out = (float*)d_out;

    void *p_xh, *p_W4, *p_Wout, *p_gates, *p_hnew, *p_logits, *p_bias4;
    cudaGetSymbolAddress(&p_xh,     g_xh);
    cudaGetSymbolAddress(&p_W4,     g_W4);
    cudaGetSymbolAddress(&p_Wout,   g_Wout);
    cudaGetSymbolAddress(&p_gates,  g_gates);
    cudaGetSymbolAddress(&p_hnew,   g_hnew);
    cudaGetSymbolAddress(&p_logits, g_logits);
    cudaGetSymbolAddress(&p_bias4,  g_bias4);

    cudaFuncSetAttribute(gemm_hmma<0>, cudaFuncAttributeMaxDynamicSharedMemorySize, GEMM_SMEM);
    cudaFuncSetAttribute(gemm_hmma<1>, cudaFuncAttributeMaxDynamicSharedMemorySize, GEMM_SMEM);

    // --- fp32 -> fp16 staging ---
    pack_xh_k<<<65536, 256>>>(x, h, (__half*)p_xh);
    size_t wgate = (size_t)HID * KIN;
    f2h_k<<<65536, 256>>>(Wf, (__half*)p_W4 + 0 * wgate);
    f2h_k<<<65536, 256>>>(Wi, (__half*)p_W4 + 1 * wgate);
    f2h_k<<<65536, 256>>>(Wc, (__half*)p_W4 + 2 * wgate);
    f2h_k<<<65536, 256>>>(Wo, (__half*)p_W4 + 3 * wgate);
    f2h_k<<<32768, 256>>>(Wout, (__half*)p_Wout);
    bias4_k<<<64, 256>>>(bf, bi, bc, bo, (float*)p_bias4);

    // --- GEMM1: [4096 x 8192] x [16384 x 8192]^T -> activated gates fp16 ---
    dim3 g1(BATCH / 128, N4 / 128);   // x = M fastest: B K-panels shared via L2
    gemm_hmma<0><<<g1, 256, GEMM_SMEM>>>((const __half*)p_xh, (const __half*)p_W4,
                                         KIN, N4, (const float*)p_bias4, p_gates);

    // --- elementwise LSTM combine -> h_new fp16 ---
    combine_k<<<32768, 256>>>((const __half*)p_gates, c, (__half*)p_hnew);

    // --- GEMM2: [4096 x 4096] x [4096 x 4096]^T -> logits fp32 ---
    dim3 g2(BATCH / 128, VOC / 128);
    gemm_hmma<1><<<g2, 256, GEMM_SMEM>>>((const __half*)p_hnew, (const __half*)p_Wout,
                                         HID, VOC, bout, p_logits);

    // --- row softmax -> probs fp32 ---
    softmax_k<<<BATCH, 256>>>((const float*)p_logits, out);
}